// round 5
// baseline (speedup 1.0000x reference)
#include <cuda_runtime.h>
#include <cstdint>

// out = joints @ R + t, R = RX(roll) @ RY(pitch) @ RZ(yaw)

struct Rot {
    float r00, r01, r02;
    float r10, r11, r12;
    float r20, r21, r22;
    float tx, ty, tz;
};

__device__ __forceinline__ Rot make_rot(const float* __restrict__ ori,
                                        const float* __restrict__ trs) {
    float sr, cr, sp, cp, sy, cy;
    sincosf(ori[0], &sr, &cr);
    sincosf(ori[1], &sp, &cp);
    sincosf(ori[2], &sy, &cy);
    Rot R;
    R.r00 = cp * cy;                R.r01 = -cp * sy;               R.r02 = sp;
    R.r10 = cr * sy + sr * sp * cy; R.r11 = cr * cy - sr * sp * sy; R.r12 = -sr * cp;
    R.r20 = sr * sy - cr * sp * cy; R.r21 = sr * cy + cr * sp * sy; R.r22 = cr * cp;
    R.tx = trs[0]; R.ty = trs[1]; R.tz = trs[2];
    return R;
}

__device__ __forceinline__ void xform(const Rot& R, float x, float y, float z,
                                      float& ox, float& oy, float& oz) {
    ox = fmaf(x, R.r00, fmaf(y, R.r10, fmaf(z, R.r20, R.tx)));
    oy = fmaf(x, R.r01, fmaf(y, R.r11, fmaf(z, R.r21, R.ty)));
    oz = fmaf(x, R.r02, fmaf(y, R.r12, fmaf(z, R.r22, R.tz)));
}

__device__ __forceinline__ uint32_t smem_u32(const void* p) {
    uint32_t a;
    asm("{ .reg .u64 t; cvta.to.shared.u64 t, %1; cvt.u32.u64 %0, t; }"
        : "=r"(a) : "l"(p));
    return a;
}

__device__ __forceinline__ void mbar_wait(uint32_t m_addr, int parity) {
    uint32_t done;
    asm volatile(
        "{\n\t.reg .pred p;\n\t"
        "mbarrier.try_wait.parity.acquire.cta.shared::cta.b64 p, [%1], %2;\n\t"
        "selp.b32 %0, 1, 0, p;\n\t}"
        : "=r"(done) : "r"(m_addr), "r"(parity) : "memory");
    if (!done) {
        asm volatile(
            "{\n\t.reg .pred P1;\n\t"
            "W%=:\n\t"
            "mbarrier.try_wait.parity.acquire.cta.shared::cta.b64 P1, [%0], %1, 0x989680;\n\t"
            "@P1 bra.uni D%=;\n\t"
            "bra.uni W%=;\n\t"
            "D%=:\n\t}"
            :: "r"(m_addr), "r"(parity) : "memory");
    }
}

// Tile = 768 float4 = 12KB = 1024 points. 3-deep smem pipeline.
// Schedule: prime loads tiles 0,1 (depth NBUF-1). At iteration k:
//   wait tile k (buf k%3) -> transform -> sync -> commit store k
//   -> wait_group 1 (store k-1 done, frees buf (k+2)%3) -> load tile k+2.
static constexpr int TILE_F4    = 768;
static constexpr int TILE_BYTES = TILE_F4 * 16;  // 12288
static constexpr int NBUF       = 3;

__global__ void __launch_bounds__(256)
transform_pipe(const float* __restrict__ in, float* __restrict__ out,
               const float* __restrict__ ori, const float* __restrict__ trs,
               int ntiles) {
    __shared__ __align__(16) float4 s[NBUF][TILE_F4];
    __shared__ __align__(8) uint64_t mbar[NBUF];

    const int t = threadIdx.x;
    uint32_t m_addr[NBUF];
#pragma unroll
    for (int i = 0; i < NBUF; i++) m_addr[i] = smem_u32(&mbar[i]);
    uint32_t s_addr[NBUF];
#pragma unroll
    for (int i = 0; i < NBUF; i++) s_addr[i] = smem_u32(&s[i][0]);

    if (t == 0) {
#pragma unroll
        for (int i = 0; i < NBUF; i++)
            asm volatile("mbarrier.init.shared.b64 [%0], 1;" :: "r"(m_addr[i]) : "memory");
    }
    __syncthreads();

    const Rot R = make_rot(ori, trs);

    const int step = gridDim.x;
    const int first = blockIdx.x;
    const int nloc = (ntiles > first) ? (ntiles - first - 1) / step + 1 : 0;

    // Prime the pipeline: NBUF-1 loads in flight (tiles 0 and 1).
    if (t == 0) {
        for (int k = 0; k < NBUF - 1 && k < nloc; k++) {
            const char* gsrc = (const char*)in + ((long)first + (long)k * step) * TILE_BYTES;
            asm volatile("mbarrier.arrive.expect_tx.shared.b64 _, [%0], %1;"
                         :: "r"(m_addr[k]), "r"(TILE_BYTES) : "memory");
            asm volatile("cp.async.bulk.shared::cta.global.mbarrier::complete_tx::bytes "
                         "[%0], [%1], %2, [%3];"
                         :: "r"(s_addr[k]), "l"(gsrc), "r"(TILE_BYTES), "r"(m_addr[k])
                         : "memory");
        }
    }

    for (int k = 0; k < nloc; k++) {
        const int b  = k % NBUF;
        const int ph = (k / NBUF) & 1;

        mbar_wait(m_addr[b], ph);

        // Each thread: 3 consecutive float4s = 4 points, in place.
        {
            float4 a = s[b][3 * t + 0];
            float4 v = s[b][3 * t + 1];
            float4 c = s[b][3 * t + 2];
            float4 oa, ob, oc;
            xform(R, a.x, a.y, a.z, oa.x, oa.y, oa.z);
            xform(R, a.w, v.x, v.y, oa.w, ob.x, ob.y);
            xform(R, v.z, v.w, c.x, ob.z, ob.w, oc.x);
            xform(R, c.y, c.z, c.w, oc.y, oc.z, oc.w);
            s[b][3 * t + 0] = oa;
            s[b][3 * t + 1] = ob;
            s[b][3 * t + 2] = oc;
        }
        __syncthreads();

        if (t == 0) {
            char* gdst = (char*)out + ((long)first + (long)k * step) * TILE_BYTES;
            asm volatile("fence.proxy.async.shared::cta;" ::: "memory");
            asm volatile("cp.async.bulk.global.shared::cta.bulk_group [%0], [%1], %2;"
                         :: "l"(gdst), "r"(s_addr[b]), "r"(TILE_BYTES) : "memory");
            asm volatile("cp.async.bulk.commit_group;" ::: "memory");

            const int kn = k + NBUF - 1;   // next load target: buf (k+2)%3
            if (kn < nloc) {
                // Stores complete in commit order: wait_group 1 -> store k-1
                // done; store k-1 owned buf (k+2)%3 = the load target.
                asm volatile("cp.async.bulk.wait_group 1;" ::: "memory");
                const int bn = kn % NBUF;
                const char* gsrc = (const char*)in + ((long)first + (long)kn * step) * TILE_BYTES;
                asm volatile("mbarrier.arrive.expect_tx.shared.b64 _, [%0], %1;"
                             :: "r"(m_addr[bn]), "r"(TILE_BYTES) : "memory");
                asm volatile("cp.async.bulk.shared::cta.global.mbarrier::complete_tx::bytes "
                             "[%0], [%1], %2, [%3];"
                             :: "r"(s_addr[bn]), "l"(gsrc), "r"(TILE_BYTES), "r"(m_addr[bn])
                             : "memory");
            }
        }
    }

    if (t == 0) {
        asm volatile("cp.async.bulk.wait_group 0;" ::: "memory");
#pragma unroll
        for (int i = 0; i < NBUF; i++)
            asm volatile("mbarrier.inval.shared.b64 [%0];" :: "r"(m_addr[i]) : "memory");
    }
}

// Scalar tail: one thread per remaining point.
__global__ void transform_tail(const float* __restrict__ in, float* __restrict__ out,
                               const float* __restrict__ ori, const float* __restrict__ trs,
                               int start_pt, int n_pts) {
    int p = start_pt + blockIdx.x * blockDim.x + threadIdx.x;
    if (p >= n_pts) return;
    Rot R = make_rot(ori, trs);
    long o = 3L * p;
    float x = in[o], y = in[o + 1], z = in[o + 2];
    float ox, oy, oz;
    xform(R, x, y, z, ox, oy, oz);
    out[o] = ox; out[o + 1] = oy; out[o + 2] = oz;
}

extern "C" void kernel_launch(void* const* d_in, const int* in_sizes, int n_in,
                              void* d_out, int out_size) {
    const float* joints = (const float*)d_in[0];
    const float* ori    = (const float*)d_in[1];
    const float* trs    = (const float*)d_in[2];
    float* out = (float*)d_out;

    const int n_floats = in_sizes[0];
    const int n_points = n_floats / 3;

    const int floats_per_tile = TILE_F4 * 4;          // 3072
    const int ntiles = n_floats / floats_per_tile;    // 13780 for this shape

    if (ntiles > 0) {
        int grid = 148 * 6;                           // persistent, 6 CTAs/SM
        if (grid > ntiles) grid = ntiles;
        transform_pipe<<<grid, 256>>>(joints, out, ori, trs, ntiles);
    }

    const int done_pts = ntiles * (floats_per_tile / 3);  // 1024 points/tile
    const int tail = n_points - done_pts;
    if (tail > 0) {
        int blocks = (tail + 255) / 256;
        transform_tail<<<blocks, 256>>>(joints, out, ori, trs, done_pts, n_points);
    }
}

// round 6
// speedup vs baseline: 1.1447x; 1.1447x over previous
#include <cuda_runtime.h>
#include <cstdint>

// out = joints @ R + t, R = RX(roll) @ RY(pitch) @ RZ(yaw)

struct Rot {
    float r00, r01, r02;
    float r10, r11, r12;
    float r20, r21, r22;
    float tx, ty, tz;
};

__device__ __forceinline__ Rot make_rot(const float* __restrict__ ori,
                                        const float* __restrict__ trs) {
    float sr, cr, sp, cp, sy, cy;
    sincosf(ori[0], &sr, &cr);
    sincosf(ori[1], &sp, &cp);
    sincosf(ori[2], &sy, &cy);
    Rot R;
    R.r00 = cp * cy;                R.r01 = -cp * sy;               R.r02 = sp;
    R.r10 = cr * sy + sr * sp * cy; R.r11 = cr * cy - sr * sp * sy; R.r12 = -sr * cp;
    R.r20 = sr * sy - cr * sp * cy; R.r21 = sr * cy + cr * sp * sy; R.r22 = cr * cp;
    R.tx = trs[0]; R.ty = trs[1]; R.tz = trs[2];
    return R;
}

__device__ __forceinline__ void xform(const Rot& R, float x, float y, float z,
                                      float& ox, float& oy, float& oz) {
    ox = fmaf(x, R.r00, fmaf(y, R.r10, fmaf(z, R.r20, R.tx)));
    oy = fmaf(x, R.r01, fmaf(y, R.r11, fmaf(z, R.r21, R.ty)));
    oz = fmaf(x, R.r02, fmaf(y, R.r12, fmaf(z, R.r22, R.tz)));
}

__device__ __forceinline__ uint32_t smem_u32(const void* p) {
    uint32_t a;
    asm("{ .reg .u64 t; cvta.to.shared.u64 t, %1; cvt.u32.u64 %0, t; }"
        : "=r"(a) : "l"(p));
    return a;
}

// Tile = 768 float4 = 12KB = 1024 points. One tile per CTA, single-shot:
// TMA in -> in-place transform -> TMA out. CTA-level concurrency (8/SM)
// provides the latency hiding; no software pipeline.
static constexpr int TILE_F4    = 768;
static constexpr int TILE_BYTES = TILE_F4 * 16;  // 12288

__global__ void __launch_bounds__(256)
transform_tile(const float* __restrict__ in, float* __restrict__ out,
               const float* __restrict__ ori, const float* __restrict__ trs,
               int ntiles, int n_pts) {
    __shared__ __align__(16) float4 s[TILE_F4];
    __shared__ __align__(8) uint64_t mbar;

    const int t   = threadIdx.x;
    const int bid = blockIdx.x;

    if (bid >= ntiles) {
        // Tail block: scalar path for points beyond the full tiles.
        const int start = ntiles * (TILE_F4 * 4 / 3);
        const Rot R = make_rot(ori, trs);
        for (int p = start + t; p < n_pts; p += 256) {
            long o = 3L * p;
            float x = in[o], y = in[o + 1], z = in[o + 2];
            float ox, oy, oz;
            xform(R, x, y, z, ox, oy, oz);
            out[o] = ox; out[o + 1] = oy; out[o + 2] = oz;
        }
        return;
    }

    const uint32_t s_addr = smem_u32(s);
    const uint32_t m_addr = smem_u32(&mbar);
    const char* gsrc = (const char*)in + (long)bid * TILE_BYTES;
    char*       gdst = (char*)out      + (long)bid * TILE_BYTES;

    // Thread 0: init barrier and immediately launch the bulk load — no
    // block-wide barrier on the load-issue path.
    if (t == 0) {
        asm volatile("mbarrier.init.shared.b64 [%0], 1;" :: "r"(m_addr) : "memory");
        asm volatile("fence.proxy.async.shared::cta;" ::: "memory");
        asm volatile("mbarrier.arrive.expect_tx.shared.b64 _, [%0], %1;"
                     :: "r"(m_addr), "r"(TILE_BYTES) : "memory");
        asm volatile("cp.async.bulk.shared::cta.global.mbarrier::complete_tx::bytes "
                     "[%0], [%1], %2, [%3];"
                     :: "r"(s_addr), "l"(gsrc), "r"(TILE_BYTES), "r"(m_addr)
                     : "memory");
    }

    // Rotation matrix (MUFU) overlaps the bulk load.
    const Rot R = make_rot(ori, trs);

    // Make barrier init visible to all threads before they wait on it.
    __syncthreads();

    // Wait for TMA completion (phase 0).
    {
        uint32_t done;
        asm volatile(
            "{\n\t.reg .pred p;\n\t"
            "mbarrier.try_wait.parity.acquire.cta.shared::cta.b64 p, [%1], 0;\n\t"
            "selp.b32 %0, 1, 0, p;\n\t}"
            : "=r"(done) : "r"(m_addr) : "memory");
        if (!done) {
            asm volatile(
                "{\n\t.reg .pred P1;\n\t"
                "W%=:\n\t"
                "mbarrier.try_wait.parity.acquire.cta.shared::cta.b64 P1, [%0], 0, 0x989680;\n\t"
                "@P1 bra.uni D%=;\n\t"
                "bra.uni W%=;\n\t"
                "D%=:\n\t}"
                :: "r"(m_addr) : "memory");
        }
    }

    // Each thread: 3 consecutive float4s = 4 points. 48B stride ->
    // conflict-free LDS.128/STS.128. In-place transform.
    {
        float4 a = s[3 * t + 0];
        float4 b = s[3 * t + 1];
        float4 c = s[3 * t + 2];
        float4 oa, ob, oc;
        xform(R, a.x, a.y, a.z, oa.x, oa.y, oa.z);
        xform(R, a.w, b.x, b.y, oa.w, ob.x, ob.y);
        xform(R, b.z, b.w, c.x, ob.z, ob.w, oc.x);
        xform(R, c.y, c.z, c.w, oc.y, oc.z, oc.w);
        s[3 * t + 0] = oa;
        s[3 * t + 1] = ob;
        s[3 * t + 2] = oc;
    }
    __syncthreads();

    if (t == 0) {
        asm volatile("fence.proxy.async.shared::cta;" ::: "memory");
        asm volatile("cp.async.bulk.global.shared::cta.bulk_group [%0], [%1], %2;"
                     :: "l"(gdst), "r"(s_addr), "r"(TILE_BYTES) : "memory");
        asm volatile("cp.async.bulk.commit_group;" ::: "memory");
        asm volatile("cp.async.bulk.wait_group 0;" ::: "memory");
        asm volatile("mbarrier.inval.shared.b64 [%0];" :: "r"(m_addr) : "memory");
    }
}

extern "C" void kernel_launch(void* const* d_in, const int* in_sizes, int n_in,
                              void* d_out, int out_size) {
    const float* joints = (const float*)d_in[0];
    const float* ori    = (const float*)d_in[1];
    const float* trs    = (const float*)d_in[2];
    float* out = (float*)d_out;

    const int n_floats = in_sizes[0];
    const int n_points = n_floats / 3;

    const int floats_per_tile = TILE_F4 * 4;          // 3072 (= 1024 points)
    const int ntiles = n_floats / floats_per_tile;    // 13780 exact for this shape
    const int tail_pts = n_points - ntiles * (floats_per_tile / 3);

    const int grid = ntiles + (tail_pts > 0 ? 1 : 0);
    if (grid > 0) {
        transform_tile<<<grid, 256>>>(joints, out, ori, trs, ntiles, n_points);
    }
}